// round 1
// baseline (speedup 1.0000x reference)
#include <cuda_runtime.h>
#include <cstdint>

#define NBATCH 16
#define CIN    512
#define CM     512
#define CN     128
#define HW     3136   // 56*56, = 49*64

// ---------------------------------------------------------------------------
// Scratch (static device globals; no allocation in kernel_launch)
// ---------------------------------------------------------------------------
__device__ float g_B [NBATCH * (size_t)CN * HW];   // Bf then attB, channel-major [b][n][p]
__device__ float g_V [NBATCH * (size_t)HW * CN];   // Vf then attV, pixel-major  [b][p][n]
__device__ float g_xB[NBATCH * (size_t)CIN * CN];  // x @ attB^T   [b][c][n]
__device__ float g_G [NBATCH * (size_t)CM * CN];   // global descriptors [b][m][n]

// ---------------------------------------------------------------------------
// Kernel 1: Bf = wB@x + bB (channel-major out), Vf = wV@x + bV (pixel-major out)
// Treated as one 256 x 3136 GEMM over K=512 per batch image.
// 64x64 tile, 256 threads, 4x4 micro.
// ---------------------------------------------------------------------------
__global__ __launch_bounds__(256) void k_bv_gemm(
    const float* __restrict__ x,
    const float* __restrict__ wB, const float* __restrict__ bB,
    const float* __restrict__ wV, const float* __restrict__ bV)
{
    const int b  = blockIdx.z;
    const int m0 = blockIdx.y * 64;      // 0,64,128,192 (combined B|V rows)
    const int p0 = blockIdx.x * 64;
    const float* __restrict__ X = x + (size_t)b * CIN * HW;
    const bool  isB = (m0 < 128);
    const float* __restrict__ W  = isB ? wB : wV;
    const int   mw0 = isB ? m0 : (m0 - 128);

    __shared__ float As[16][64];   // [k][m]
    __shared__ float Bs[16][64];   // [k][p]

    const int t  = threadIdx.x;
    const int tx = t & 15, ty = t >> 4;
    const int am = t >> 2,  aq = (t & 3) * 4;    // W tile load: 64 rows x 16 k
    const int bk = t >> 4,  bq = (t & 15) * 4;   // X tile load: 16 k x 64 p

    float acc[4][4] = {};

    for (int k0 = 0; k0 < CIN; k0 += 16) {
        float4 av = *(const float4*)&W[(size_t)(mw0 + am) * CIN + k0 + aq];
        float4 bv = *(const float4*)&X[(size_t)(k0 + bk) * HW + p0 + bq];
        __syncthreads();
        As[aq + 0][am] = av.x; As[aq + 1][am] = av.y;
        As[aq + 2][am] = av.z; As[aq + 3][am] = av.w;
        *(float4*)&Bs[bk][bq] = bv;
        __syncthreads();
        #pragma unroll
        for (int k = 0; k < 16; ++k) {
            float4 a  = *(const float4*)&As[k][ty * 4];
            float4 bb = *(const float4*)&Bs[k][tx * 4];
            float ar[4] = {a.x, a.y, a.z, a.w};
            float br[4] = {bb.x, bb.y, bb.z, bb.w};
            #pragma unroll
            for (int i = 0; i < 4; ++i)
                #pragma unroll
                for (int j = 0; j < 4; ++j)
                    acc[i][j] += ar[i] * br[j];
        }
    }

    if (isB) {
        #pragma unroll
        for (int i = 0; i < 4; ++i) {
            const int m = m0 + ty * 4 + i;
            const float bias = bB[m];
            #pragma unroll
            for (int j = 0; j < 4; ++j) {
                const int p = p0 + tx * 4 + j;
                g_B[((size_t)b * CN + m) * HW + p] = acc[i][j] + bias;
            }
        }
    } else {
        #pragma unroll
        for (int i = 0; i < 4; ++i) {
            const int m = m0 - 128 + ty * 4 + i;
            const float bias = bV[m];
            #pragma unroll
            for (int j = 0; j < 4; ++j) {
                const int p = p0 + tx * 4 + j;
                g_V[((size_t)b * HW + p) * CN + m] = acc[i][j] + bias;  // transposed store
            }
        }
    }
}

// ---------------------------------------------------------------------------
// Kernel 2: in-place softmax over rows of length HW (attB). One block per row.
// ---------------------------------------------------------------------------
__global__ __launch_bounds__(256) void k_softmax_row(float* __restrict__ data)
{
    float* __restrict__ row = data + (size_t)blockIdx.x * HW;
    const int t = threadIdx.x;
    __shared__ float red[256];

    float m = -1e30f;
    for (int i = t; i < HW; i += 256) m = fmaxf(m, row[i]);
    red[t] = m; __syncthreads();
    for (int s = 128; s > 0; s >>= 1) {
        if (t < s) red[t] = fmaxf(red[t], red[t + s]);
        __syncthreads();
    }
    m = red[0]; __syncthreads();

    float sum = 0.f;
    for (int i = t; i < HW; i += 256) {
        float e = __expf(row[i] - m);
        row[i] = e;
        sum += e;
    }
    red[t] = sum; __syncthreads();
    for (int s = 128; s > 0; s >>= 1) {
        if (t < s) red[t] += red[t + s];
        __syncthreads();
    }
    const float inv = 1.0f / red[0];
    for (int i = t; i < HW; i += 256) row[i] *= inv;
}

// ---------------------------------------------------------------------------
// Kernel 3: in-place softmax over contiguous rows of 128 (attV). Warp per row.
// ---------------------------------------------------------------------------
__global__ __launch_bounds__(256) void k_softmax128(float* __restrict__ data, int nrows)
{
    const int row  = (blockIdx.x * blockDim.x + threadIdx.x) >> 5;
    if (row >= nrows) return;
    const int lane = threadIdx.x & 31;
    float4* rp = (float4*)(data + (size_t)row * CN) + lane;
    float4 v = *rp;

    float m = fmaxf(fmaxf(v.x, v.y), fmaxf(v.z, v.w));
    #pragma unroll
    for (int o = 16; o > 0; o >>= 1) m = fmaxf(m, __shfl_xor_sync(0xFFFFFFFFu, m, o));

    float ex = __expf(v.x - m), ey = __expf(v.y - m);
    float ez = __expf(v.z - m), ew = __expf(v.w - m);
    float s = ex + ey + ez + ew;
    #pragma unroll
    for (int o = 16; o > 0; o >>= 1) s += __shfl_xor_sync(0xFFFFFFFFu, s, o);

    const float inv = 1.0f / s;
    v.x = ex * inv; v.y = ey * inv; v.z = ez * inv; v.w = ew * inv;
    *rp = v;
}

// ---------------------------------------------------------------------------
// Kernel 4/6: generic TN GEMM  C[m][n] = sum_k A[m][k] * B[n][k]
// A: M x Kd (row-major), B: N x Kd (row-major), C: M x N row-major.
// 64x64 tile, BK=32, 256 threads, 4x4 micro. Batched via blockIdx.z + strides.
// Requires M,N % 64 == 0 and Kd % 32 == 0.
// ---------------------------------------------------------------------------
__global__ __launch_bounds__(256) void k_gemm_tn(
    const float* __restrict__ A, const float* __restrict__ B, float* __restrict__ C,
    int M, int N, int Kd,
    long long sA, long long sB, long long sC)
{
    const int b = blockIdx.z;
    A += (size_t)b * sA; B += (size_t)b * sB; C += (size_t)b * sC;
    const int m0 = blockIdx.y * 64;
    const int n0 = blockIdx.x * 64;

    __shared__ float As[32][64];   // [k][m]
    __shared__ float Bs[32][64];   // [k][n]

    const int t  = threadIdx.x;
    const int tx = t & 15, ty = t >> 4;
    const int r0 = t >> 3;          // 0..31
    const int r1 = r0 + 32;         // 32..63
    const int q  = (t & 7) * 4;     // k offset within BK=32

    float acc[4][4] = {};

    for (int k0 = 0; k0 < Kd; k0 += 32) {
        float4 a0 = *(const float4*)&A[(size_t)(m0 + r0) * Kd + k0 + q];
        float4 a1 = *(const float4*)&A[(size_t)(m0 + r1) * Kd + k0 + q];
        float4 b0 = *(const float4*)&B[(size_t)(n0 + r0) * Kd + k0 + q];
        float4 b1 = *(const float4*)&B[(size_t)(n0 + r1) * Kd + k0 + q];
        __syncthreads();
        As[q + 0][r0] = a0.x; As[q + 1][r0] = a0.y; As[q + 2][r0] = a0.z; As[q + 3][r0] = a0.w;
        As[q + 0][r1] = a1.x; As[q + 1][r1] = a1.y; As[q + 2][r1] = a1.z; As[q + 3][r1] = a1.w;
        Bs[q + 0][r0] = b0.x; Bs[q + 1][r0] = b0.y; Bs[q + 2][r0] = b0.z; Bs[q + 3][r0] = b0.w;
        Bs[q + 0][r1] = b1.x; Bs[q + 1][r1] = b1.y; Bs[q + 2][r1] = b1.z; Bs[q + 3][r1] = b1.w;
        __syncthreads();
        #pragma unroll
        for (int k = 0; k < 32; ++k) {
            float4 a  = *(const float4*)&As[k][ty * 4];
            float4 bb = *(const float4*)&Bs[k][tx * 4];
            float ar[4] = {a.x, a.y, a.z, a.w};
            float br[4] = {bb.x, bb.y, bb.z, bb.w};
            #pragma unroll
            for (int i = 0; i < 4; ++i)
                #pragma unroll
                for (int j = 0; j < 4; ++j)
                    acc[i][j] += ar[i] * br[j];
        }
    }

    #pragma unroll
    for (int i = 0; i < 4; ++i)
        #pragma unroll
        for (int j = 0; j < 4; ++j)
            C[(size_t)(m0 + ty * 4 + i) * N + n0 + tx * 4 + j] = acc[i][j];
}

// ---------------------------------------------------------------------------
// Kernel 5: G = wA @ xB + bA   (NN GEMM, M=512, N=128, K=512; wA unbatched)
// ---------------------------------------------------------------------------
__global__ __launch_bounds__(256) void k_gemm_nn_bias(
    const float* __restrict__ A,   // M x Kd row-major (shared across batch)
    const float* __restrict__ Bm,  // Kd x N row-major (per batch)
    const float* __restrict__ bias,
    float* __restrict__ C,
    int N, int Kd, long long sB, long long sC)
{
    const int b = blockIdx.z;
    Bm += (size_t)b * sB; C += (size_t)b * sC;
    const int m0 = blockIdx.y * 64;
    const int n0 = blockIdx.x * 64;

    __shared__ float As[16][64];
    __shared__ float Bs[16][64];

    const int t  = threadIdx.x;
    const int tx = t & 15, ty = t >> 4;
    const int am = t >> 2,  aq = (t & 3) * 4;
    const int bk = t >> 4,  bq = (t & 15) * 4;

    float acc[4][4] = {};

    for (int k0 = 0; k0 < Kd; k0 += 16) {
        float4 av = *(const float4*)&A [(size_t)(m0 + am) * Kd + k0 + aq];
        float4 bv = *(const float4*)&Bm[(size_t)(k0 + bk) * N  + n0 + bq];
        __syncthreads();
        As[aq + 0][am] = av.x; As[aq + 1][am] = av.y;
        As[aq + 2][am] = av.z; As[aq + 3][am] = av.w;
        *(float4*)&Bs[bk][bq] = bv;
        __syncthreads();
        #pragma unroll
        for (int k = 0; k < 16; ++k) {
            float4 a  = *(const float4*)&As[k][ty * 4];
            float4 bb = *(const float4*)&Bs[k][tx * 4];
            float ar[4] = {a.x, a.y, a.z, a.w};
            float br[4] = {bb.x, bb.y, bb.z, bb.w};
            #pragma unroll
            for (int i = 0; i < 4; ++i)
                #pragma unroll
                for (int j = 0; j < 4; ++j)
                    acc[i][j] += ar[i] * br[j];
        }
    }

    #pragma unroll
    for (int i = 0; i < 4; ++i) {
        const int m = m0 + ty * 4 + i;
        const float bv = bias[m];
        #pragma unroll
        for (int j = 0; j < 4; ++j)
            C[(size_t)m * N + n0 + tx * 4 + j] = acc[i][j] + bv;
    }
}

// ---------------------------------------------------------------------------
// Launch
// ---------------------------------------------------------------------------
extern "C" void kernel_launch(void* const* d_in, const int* in_sizes, int n_in,
                              void* d_out, int out_size)
{
    const float* x  = (const float*)d_in[0];
    const float* wA = (const float*)d_in[1];
    const float* bA = (const float*)d_in[2];
    const float* wB = (const float*)d_in[3];
    const float* bB = (const float*)d_in[4];
    const float* wV = (const float*)d_in[5];
    const float* bV = (const float*)d_in[6];
    float* out = (float*)d_out;

    float *pB, *pV, *pxB, *pG;
    cudaGetSymbolAddress((void**)&pB,  g_B);
    cudaGetSymbolAddress((void**)&pV,  g_V);
    cudaGetSymbolAddress((void**)&pxB, g_xB);
    cudaGetSymbolAddress((void**)&pG,  g_G);

    // 1) Bf (channel-major) and Vf (pixel-major): combined 256 x 3136 GEMM, K=512
    k_bv_gemm<<<dim3(HW / 64, 4, NBATCH), 256>>>(x, wB, bB, wV, bV);

    // 2) attB: softmax over spatial dim (rows of 3136)
    k_softmax_row<<<NBATCH * CN, 256>>>(pB);

    // 3) attV: softmax over channel dim (contiguous rows of 128)
    {
        const int nrows = NBATCH * HW;
        const int blocks = (nrows * 32 + 255) / 256;
        k_softmax128<<<blocks, 256>>>(pV, nrows);
    }

    // 4) xB[c][n] = sum_p x[c][p] * attB[n][p]   (M=512, N=128, Kd=3136)
    k_gemm_tn<<<dim3(CN / 64, CIN / 64, NBATCH), 256>>>(
        x, pB, pxB, CIN, CN, HW,
        (long long)CIN * HW, (long long)CN * HW, (long long)CIN * CN);

    // 5) G = wA @ xB + bA   (M=512, N=128, Kd=512)
    k_gemm_nn_bias<<<dim3(CN / 64, CM / 64, NBATCH), 256>>>(
        wA, pxB, bA, pG, CN, CIN,
        (long long)CIN * CN, (long long)CM * CN);

    // 6) Z[m][p] = sum_n G[m][n] * attV[p][n]   (M=512, N=3136, Kd=128) -> d_out
    k_gemm_tn<<<dim3(HW / 64, CM / 64, NBATCH), 256>>>(
        pG, pV, out, CM, HW, CN,
        (long long)CM * CN, (long long)HW * CN, (long long)CM * HW);

    (void)in_sizes; (void)n_in; (void)out_size;
}

// round 3
// speedup vs baseline: 1.3156x; 1.3156x over previous
#include <cuda_runtime.h>
#include <cuda_bf16.h>
#include <cstdint>

#define NBATCH 16
#define CIN    512
#define CM     512
#define CN     128
#define HW     3136   // 56*56 = 49*64

// ---------------------------------------------------------------------------
// Scratch
// ---------------------------------------------------------------------------
__device__ float g_B  [NBATCH * (size_t)CN * HW];   // Bf / attB  [b][n][p]
__device__ float g_V  [NBATCH * (size_t)HW * CN];   // Vf / attV  [b][p][n]
__device__ float g_xBT[NBATCH * (size_t)CN * CIN];  // (x @ attB^T)^T  [b][n][c]
__device__ float g_G  [NBATCH * (size_t)CM * CN];   // G  [b][m][n]

// ---------------------------------------------------------------------------
// helpers
// ---------------------------------------------------------------------------
__device__ __forceinline__ uint32_t smem_u32(const void* p) {
    uint32_t a;
    asm("{ .reg .u64 t; cvta.to.shared.u64 t, %1; cvt.u32.u64 %0, t; }"
        : "=r"(a) : "l"(p));
    return a;
}

// fp32 -> (hi bf16, lo bf16): two packed
__device__ __forceinline__ void split2(float f0, float f1, uint32_t& hi, uint32_t& lo) {
    __nv_bfloat16 h0 = __float2bfloat16_rn(f0);
    __nv_bfloat16 h1 = __float2bfloat16_rn(f1);
    float r0 = f0 - __bfloat162float(h0);
    float r1 = f1 - __bfloat162float(h1);
    __nv_bfloat16 l0 = __float2bfloat16_rn(r0);
    __nv_bfloat16 l1 = __float2bfloat16_rn(r1);
    hi = (uint32_t)__bfloat16_as_ushort(h0) | ((uint32_t)__bfloat16_as_ushort(h1) << 16);
    lo = (uint32_t)__bfloat16_as_ushort(l0) | ((uint32_t)__bfloat16_as_ushort(l1) << 16);
}
__device__ __forceinline__ void split1(float f, uint16_t& hi, uint16_t& lo) {
    __nv_bfloat16 h = __float2bfloat16_rn(f);
    float r = f - __bfloat162float(h);
    __nv_bfloat16 l = __float2bfloat16_rn(r);
    hi = __bfloat16_as_ushort(h);
    lo = __bfloat16_as_ushort(l);
}

__device__ __forceinline__ void ldsm_x4(uint32_t& r0, uint32_t& r1,
                                        uint32_t& r2, uint32_t& r3, uint32_t addr) {
    asm volatile("ldmatrix.sync.aligned.m8n8.x4.shared.b16 {%0,%1,%2,%3}, [%4];"
                 : "=r"(r0), "=r"(r1), "=r"(r2), "=r"(r3) : "r"(addr));
}

__device__ __forceinline__ void mma16816(float* d, const uint32_t* a,
                                         uint32_t b0, uint32_t b1) {
    asm volatile(
        "mma.sync.aligned.m16n8k16.row.col.f32.bf16.bf16.f32 "
        "{%0,%1,%2,%3}, {%4,%5,%6,%7}, {%8,%9}, {%0,%1,%2,%3};"
        : "+f"(d[0]), "+f"(d[1]), "+f"(d[2]), "+f"(d[3])
        : "r"(a[0]), "r"(a[1]), "r"(a[2]), "r"(a[3]), "r"(b0), "r"(b1));
}

// ---------------------------------------------------------------------------
// Generic tensor-core GEMM: D[m][n] = sum_k A[m][k] * B[n][k]
//   Block tile M=128 x N=64, K-chunk=32. 256 threads = 8 warps (4 m x 2 n),
//   warp tile 32x32 = 2x4 m16n8k16 tiles. bf16 split-float (3 MMA / product).
//   A: K-major rows (stride Kd).
//   B: bmode 0 -> K-major rows (stride Kd); bmode 1 -> B(n,k) = Bp[k*bks + n].
//   Epilogue via SMEM: trans 0 -> C[m*ldc+n]; trans 1 -> C[n*ldc+m]. bias[m] opt.
// ---------------------------------------------------------------------------
#define APITCH 40            // bf16 elements per row (80 bytes) -> conflict-free ldmatrix
#define SM_AH  0             // [128][40] bf16
#define SM_AL  (128 * APITCH)
#define SM_BH  (2 * 128 * APITCH)
#define SM_BL  (2 * 128 * APITCH + 64 * APITCH)
#define SM_ELEMS (2 * 128 * APITCH + 2 * 64 * APITCH)   // 15360 bf16 = 30720 B
#define EPITCH 68
#define SMEM_BYTES (128 * EPITCH * 4)                    // 34816 B (>= tile area)

__global__ __launch_bounds__(256) void k_mma(
    const float* __restrict__ A, const float* __restrict__ B,
    float* __restrict__ C, const float* __restrict__ bias,
    int Kd, int ldc, int bmode, int bks, int trans,
    long long sA, long long sB, long long sC)
{
    extern __shared__ char smraw[];
    __nv_bfloat16* const smb = (__nv_bfloat16*)smraw;
    const int b = blockIdx.z;
    A += (size_t)b * sA; B += (size_t)b * sB; C += (size_t)b * sC;
    const int m0 = blockIdx.y * 128;
    const int n0 = blockIdx.x * 64;
    const int tid = threadIdx.x, wid = tid >> 5, lane = tid & 31;
    const int warp_m = wid & 3, warp_n = wid >> 2;

    const uint32_t sbase = smem_u32(smraw);
    // ldmatrix base address components (per this thread)
    const int lrow = lane & 15;          // row within 16-row group
    const int lgr  = lane >> 4;          // granule half

    float acc[2][4][4] = {};

    for (int k0 = 0; k0 < Kd; k0 += 32) {
        // ---- load A tile: 128 rows x 32 k ----
        #pragma unroll 2
        for (int i = tid; i < 1024; i += 256) {
            const int r = i >> 3, kq = (i & 7) << 2;
            float4 v = *(const float4*)&A[(size_t)(m0 + r) * Kd + k0 + kq];
            uint32_t h0, l0, h1, l1;
            split2(v.x, v.y, h0, l0);
            split2(v.z, v.w, h1, l1);
            *(uint2*)(smb + SM_AH + r * APITCH + kq) = make_uint2(h0, h1);
            *(uint2*)(smb + SM_AL + r * APITCH + kq) = make_uint2(l0, l1);
        }
        // ---- load B tile: 64 rows x 32 k ----
        if (bmode == 0) {
            for (int i = tid; i < 512; i += 256) {
                const int r = i >> 3, kq = (i & 7) << 2;
                float4 v = *(const float4*)&B[(size_t)(n0 + r) * Kd + k0 + kq];
                uint32_t h0, l0, h1, l1;
                split2(v.x, v.y, h0, l0);
                split2(v.z, v.w, h1, l1);
                *(uint2*)(smb + SM_BH + r * APITCH + kq) = make_uint2(h0, h1);
                *(uint2*)(smb + SM_BL + r * APITCH + kq) = make_uint2(l0, l1);
            }
        } else {
            for (int i = tid; i < 512; i += 256) {
                const int kk = i & 31, ng = i >> 5;
                const int n = ng << 2;
                float4 v = *(const float4*)&B[(size_t)(k0 + kk) * bks + n0 + n];
                float fv[4] = {v.x, v.y, v.z, v.w};
                #pragma unroll
                for (int j = 0; j < 4; ++j) {
                    uint16_t h, l;
                    split1(fv[j], h, l);
                    *((uint16_t*)smb + SM_BH + (n + j) * APITCH + kk) = h;
                    *((uint16_t*)smb + SM_BL + (n + j) * APITCH + kk) = l;
                }
            }
        }
        __syncthreads();

        // ---- MMA over 2 k-steps of 16 ----
        #pragma unroll
        for (int ks = 0; ks < 2; ++ks) {
            const uint32_t goff = (uint32_t)((ks * 2 + lgr) * 16);  // bytes
            uint32_t ah[2][4], al[2][4];
            #pragma unroll
            for (int mt = 0; mt < 2; ++mt) {
                const int row = warp_m * 32 + mt * 16 + lrow;
                ldsm_x4(ah[mt][0], ah[mt][1], ah[mt][2], ah[mt][3],
                        sbase + (SM_AH + row * APITCH) * 2 + goff);
                ldsm_x4(al[mt][0], al[mt][1], al[mt][2], al[mt][3],
                        sbase + (SM_AL + row * APITCH) * 2 + goff);
            }
            uint32_t bh[4][2], bl[4][2];
            #pragma unroll
            for (int ng = 0; ng < 2; ++ng) {
                const int row = warp_n * 32 + ng * 16 + lrow;
                uint32_t r0, r1, r2, r3;
                ldsm_x4(r0, r1, r2, r3, sbase + (SM_BH + row * APITCH) * 2 + goff);
                bh[ng * 2 + 0][0] = r0; bh[ng * 2 + 0][1] = r2;
                bh[ng * 2 + 1][0] = r1; bh[ng * 2 + 1][1] = r3;
                ldsm_x4(r0, r1, r2, r3, sbase + (SM_BL + row * APITCH) * 2 + goff);
                bl[ng * 2 + 0][0] = r0; bl[ng * 2 + 0][1] = r2;
                bl[ng * 2 + 1][0] = r1; bl[ng * 2 + 1][1] = r3;
            }
            #pragma unroll
            for (int mt = 0; mt < 2; ++mt)
                #pragma unroll
                for (int nt = 0; nt < 4; ++nt) {
                    mma16816(acc[mt][nt], ah[mt], bh[nt][0], bh[nt][1]);
                    mma16816(acc[mt][nt], ah[mt], bl[nt][0], bl[nt][1]);
                    mma16816(acc[mt][nt], al[mt], bh[nt][0], bh[nt][1]);
                }
        }
        __syncthreads();
    }

    // ---- epilogue: stage fp32 tile in SMEM, then coalesced global stores ----
    float* const st = (float*)smraw;   // [128][EPITCH]
    {
        const int drow = lane >> 2, dcol = (lane & 3) * 2;
        #pragma unroll
        for (int mt = 0; mt < 2; ++mt) {
            const int r0w = warp_m * 32 + mt * 16 + drow;
            const float bv0 = bias ? bias[m0 + r0w]     : 0.0f;
            const float bv1 = bias ? bias[m0 + r0w + 8] : 0.0f;
            #pragma unroll
            for (int nt = 0; nt < 4; ++nt) {
                const int c = warp_n * 32 + nt * 8 + dcol;
                st[r0w * EPITCH + c]           = acc[mt][nt][0] + bv0;
                st[r0w * EPITCH + c + 1]       = acc[mt][nt][1] + bv0;
                st[(r0w + 8) * EPITCH + c]     = acc[mt][nt][2] + bv1;
                st[(r0w + 8) * EPITCH + c + 1] = acc[mt][nt][3] + bv1;
            }
        }
    }
    __syncthreads();

    if (!trans) {
        for (int i = tid; i < 128 * 16; i += 256) {
            const int r = i >> 4, q = (i & 15) << 2;
            float4 v = make_float4(st[r * EPITCH + q],     st[r * EPITCH + q + 1],
                                   st[r * EPITCH + q + 2], st[r * EPITCH + q + 3]);
            *(float4*)&C[(size_t)(m0 + r) * ldc + n0 + q] = v;
        }
    } else {
        for (int i = tid; i < 64 * 32; i += 256) {
            const int n = i >> 5, mq = (i & 31) << 2;
            float4 v = make_float4(st[(mq + 0) * EPITCH + n], st[(mq + 1) * EPITCH + n],
                                   st[(mq + 2) * EPITCH + n], st[(mq + 3) * EPITCH + n]);
            *(float4*)&C[(size_t)(n0 + n) * ldc + m0 + mq] = v;
        }
    }
}

// ---------------------------------------------------------------------------
// Softmax kernels
// ---------------------------------------------------------------------------
__global__ __launch_bounds__(256) void k_softmax_row(float* __restrict__ data)
{
    float* __restrict__ row = data + (size_t)blockIdx.x * HW;
    const int t = threadIdx.x;
    __shared__ float red[256];

    float m = -1e30f;
    for (int i = t; i < HW; i += 256) m = fmaxf(m, row[i]);
    red[t] = m; __syncthreads();
    for (int s = 128; s > 0; s >>= 1) {
        if (t < s) red[t] = fmaxf(red[t], red[t + s]);
        __syncthreads();
    }
    m = red[0]; __syncthreads();

    float sum = 0.f;
    for (int i = t; i < HW; i += 256) {
        float e = __expf(row[i] - m);
        row[i] = e;
        sum += e;
    }
    red[t] = sum; __syncthreads();
    for (int s = 128; s > 0; s >>= 1) {
        if (t < s) red[t] += red[t + s];
        __syncthreads();
    }
    const float inv = 1.0f / red[0];
    for (int i = t; i < HW; i += 256) row[i] *= inv;
}

__global__ __launch_bounds__(256) void k_softmax128(float* __restrict__ data, int nrows)
{
    const int row = (blockIdx.x * blockDim.x + threadIdx.x) >> 5;
    if (row >= nrows) return;
    const int lane = threadIdx.x & 31;
    float4* rp = (float4*)(data + (size_t)row * CN) + lane;
    float4 v = *rp;

    float m = fmaxf(fmaxf(v.x, v.y), fmaxf(v.z, v.w));
    #pragma unroll
    for (int o = 16; o > 0; o >>= 1) m = fmaxf(m, __shfl_xor_sync(0xFFFFFFFFu, m, o));

    float ex = __expf(v.x - m), ey = __expf(v.y - m);
    float ez = __expf(v.z - m), ew = __expf(v.w - m);
    float s = ex + ey + ez + ew;
    #pragma unroll
    for (int o = 16; o > 0; o >>= 1) s += __shfl_xor_sync(0xFFFFFFFFu, s, o);

    const float inv = 1.0f / s;
    v.x = ex * inv; v.y = ey * inv; v.z = ez * inv; v.w = ew * inv;
    *rp = v;
}

// ---------------------------------------------------------------------------
// Launch
// ---------------------------------------------------------------------------
extern "C" void kernel_launch(void* const* d_in, const int* in_sizes, int n_in,
                              void* d_out, int out_size)
{
    const float* x  = (const float*)d_in[0];
    const float* wA = (const float*)d_in[1];
    const float* bA = (const float*)d_in[2];
    const float* wB = (const float*)d_in[3];
    const float* bB = (const float*)d_in[4];
    const float* wV = (const float*)d_in[5];
    const float* bV = (const float*)d_in[6];
    float* out = (float*)d_out;

    float *pB, *pV, *pxBT, *pG;
    cudaGetSymbolAddress((void**)&pB,   g_B);
    cudaGetSymbolAddress((void**)&pV,   g_V);
    cudaGetSymbolAddress((void**)&pxBT, g_xBT);
    cudaGetSymbolAddress((void**)&pG,   g_G);

    cudaFuncSetAttribute(k_mma, cudaFuncAttributeMaxDynamicSharedMemorySize, SMEM_BYTES);

    // K1-B: Bf = wB @ x + bB  -> g_B [n][p]   (M=128, N=3136, K=512; B strided)
    k_mma<<<dim3(HW / 64, 1, NBATCH), 256, SMEM_BYTES>>>(
        wB, x, pB, bB, CIN, HW, /*bmode=*/1, /*bks=*/HW, /*trans=*/0,
        0, (long long)CIN * HW, (long long)CN * HW);

    // K1-V: Vf = wV @ x + bV  -> g_V [p][n]   (transposed store)
    k_mma<<<dim3(HW / 64, 1, NBATCH), 256, SMEM_BYTES>>>(
        wV, x, pV, bV, CIN, CN, /*bmode=*/1, /*bks=*/HW, /*trans=*/1,
        0, (long long)CIN * HW, (long long)HW * CN);

    // attB: softmax over spatial dim
    k_softmax_row<<<NBATCH * CN, 256>>>(pB);

    // attV: softmax over channel dim
    {
        const int nrows  = NBATCH * HW;
        const int blocks = (nrows * 32 + 255) / 256;
        k_softmax128<<<blocks, 256>>>(pV, nrows);
    }

    // K4: xBT[n][c] = sum_p x[c][p] * attB[n][p]   (M=512, N=128, K=3136; trans)
    k_mma<<<dim3(CN / 64, CIN / 128, NBATCH), 256, SMEM_BYTES>>>(
        x, pB, pxBT, nullptr, HW, CIN, /*bmode=*/0, 0, /*trans=*/1,
        (long long)CIN * HW, (long long)CN * HW, (long long)CN * CIN);

    // K5: G = wA @ xB + bA   (M=512, N=128, K=512)
    k_mma<<<dim3(CN / 64, CM / 128, NBATCH), 256, SMEM_BYTES>>>(
        wA, pxBT, pG, bA, CIN, CN, /*bmode=*/0, 0, /*trans=*/0,
        0, (long long)CN * CIN, (long long)CM * CN);

    // K6: Z[m][p] = sum_n G[m][n] * attV[p][n]   (M=512, N=3136, K=128) -> out
    k_mma<<<dim3(HW / 64, CM / 128, NBATCH), 256, SMEM_BYTES>>>(
        pG, pV, out, nullptr, CN, HW, /*bmode=*/0, 0, /*trans=*/0,
        (long long)CM * CN, (long long)HW * CN, (long long)CM * HW);

    (void)in_sizes; (void)n_in; (void)out_size;
}

// round 4
// speedup vs baseline: 2.1591x; 1.6412x over previous
#include <cuda_runtime.h>
#include <cuda_bf16.h>
#include <cstdint>

#define NBATCH 16
#define CIN    512
#define CM     512
#define CN     128
#define HW     3136   // 56*56 = 49*64

typedef __nv_bfloat16 bf16;

// ---------------------------------------------------------------------------
// Scratch (split bf16 operand pairs + fp32 pre-softmax buffers)
// ---------------------------------------------------------------------------
__device__ bf16 g_wAh[CM * CIN],  g_wAl[CM * CIN];
__device__ bf16 g_wBh[CN * CIN],  g_wBl[CN * CIN];
__device__ bf16 g_wVh[CN * CIN],  g_wVl[CN * CIN];
__device__ bf16 g_xh [NBATCH * (size_t)CIN * HW], g_xl [NBATCH * (size_t)CIN * HW];
__device__ bf16 g_xTh[NBATCH * (size_t)HW * CIN], g_xTl[NBATCH * (size_t)HW * CIN];
__device__ float g_Bf[NBATCH * (size_t)CN * HW];   // pre-softmax B  [b][n][p]
__device__ float g_Vf[NBATCH * (size_t)HW * CN];   // pre-softmax V  [b][p][n]
__device__ bf16 g_aBh[NBATCH * (size_t)CN * HW],  g_aBl[NBATCH * (size_t)CN * HW];
__device__ bf16 g_aVh[NBATCH * (size_t)HW * CN],  g_aVl[NBATCH * (size_t)HW * CN];
__device__ bf16 g_xBTh[NBATCH * (size_t)CN * CIN], g_xBTl[NBATCH * (size_t)CN * CIN];
__device__ bf16 g_Gh [NBATCH * (size_t)CM * CN],  g_Gl [NBATCH * (size_t)CM * CN];

// ---------------------------------------------------------------------------
// helpers
// ---------------------------------------------------------------------------
__device__ __forceinline__ uint32_t smem_u32(const void* p) {
    uint32_t a;
    asm("{ .reg .u64 t; cvta.to.shared.u64 t, %1; cvt.u32.u64 %0, t; }"
        : "=r"(a) : "l"(p));
    return a;
}
__device__ __forceinline__ void split1(float f, uint16_t& hi, uint16_t& lo) {
    __nv_bfloat16 h = __float2bfloat16_rn(f);
    float r = f - __bfloat162float(h);
    __nv_bfloat16 l = __float2bfloat16_rn(r);
    hi = __bfloat16_as_ushort(h);
    lo = __bfloat16_as_ushort(l);
}
__device__ __forceinline__ void split2(float f0, float f1, uint32_t& hi, uint32_t& lo) {
    uint16_t h0, l0, h1, l1;
    split1(f0, h0, l0);
    split1(f1, h1, l1);
    hi = (uint32_t)h0 | ((uint32_t)h1 << 16);
    lo = (uint32_t)l0 | ((uint32_t)l1 << 16);
}

__device__ __forceinline__ void cp16(uint32_t dst, const void* src) {
    asm volatile("cp.async.cg.shared.global [%0], [%1], 16;" :: "r"(dst), "l"(src));
}
#define CP_COMMIT() asm volatile("cp.async.commit_group;")
#define CP_WAIT1()  asm volatile("cp.async.wait_group 1;")
#define CP_WAIT0()  asm volatile("cp.async.wait_group 0;")

__device__ __forceinline__ void ldsm_x4(uint32_t& r0, uint32_t& r1,
                                        uint32_t& r2, uint32_t& r3, uint32_t addr) {
    asm volatile("ldmatrix.sync.aligned.m8n8.x4.shared.b16 {%0,%1,%2,%3}, [%4];"
                 : "=r"(r0), "=r"(r1), "=r"(r2), "=r"(r3) : "r"(addr));
}
__device__ __forceinline__ void mma16816(float* d, const uint32_t* a,
                                         uint32_t b0, uint32_t b1) {
    asm volatile(
        "mma.sync.aligned.m16n8k16.row.col.f32.bf16.bf16.f32 "
        "{%0,%1,%2,%3}, {%4,%5,%6,%7}, {%8,%9}, {%0,%1,%2,%3};"
        : "+f"(d[0]), "+f"(d[1]), "+f"(d[2]), "+f"(d[3])
        : "r"(a[0]), "r"(a[1]), "r"(a[2]), "r"(a[3]), "r"(b0), "r"(b1));
}

// ---------------------------------------------------------------------------
// Prep kernels
// ---------------------------------------------------------------------------
__global__ __launch_bounds__(256) void k_split(const float* __restrict__ src,
                                               bf16* __restrict__ h, bf16* __restrict__ l,
                                               int n)
{
    const int i = blockIdx.x * 256 + threadIdx.x;
    if (i < n) {
        uint16_t hh, ll;
        split1(src[i], hh, ll);
        ((uint16_t*)h)[i] = hh;
        ((uint16_t*)l)[i] = ll;
    }
}

// split x into [b][c][p] pair AND transposed [b][p][c] pair, one read of x
__global__ __launch_bounds__(256) void k_prepx(const float* __restrict__ x,
                                               bf16* __restrict__ xh, bf16* __restrict__ xl,
                                               bf16* __restrict__ xTh, bf16* __restrict__ xTl)
{
    __shared__ uint16_t th[32][33], tl[32][33];
    const int b  = blockIdx.z;
    const int p0 = blockIdx.x * 32;
    const int c0 = blockIdx.y * 32;
    const int tx = threadIdx.x & 31, ty = threadIdx.x >> 5;
    const size_t xoff = (size_t)b * CIN * HW;
    const size_t toff = (size_t)b * HW * CIN;

    #pragma unroll
    for (int it = 0; it < 4; ++it) {
        const int c = c0 + ty + it * 8;
        const float f = x[xoff + (size_t)c * HW + p0 + tx];
        uint16_t hh, ll;
        split1(f, hh, ll);
        ((uint16_t*)xh)[xoff + (size_t)c * HW + p0 + tx] = hh;
        ((uint16_t*)xl)[xoff + (size_t)c * HW + p0 + tx] = ll;
        th[ty + it * 8][tx] = hh;
        tl[ty + it * 8][tx] = ll;
    }
    __syncthreads();
    #pragma unroll
    for (int it = 0; it < 4; ++it) {
        const int p = p0 + ty + it * 8;
        ((uint16_t*)xTh)[toff + (size_t)p * CIN + c0 + tx] = th[tx][ty + it * 8];
        ((uint16_t*)xTl)[toff + (size_t)p * CIN + c0 + tx] = tl[tx][ty + it * 8];
    }
}

// ---------------------------------------------------------------------------
// Softmax kernels -> emit split bf16
// ---------------------------------------------------------------------------
__global__ __launch_bounds__(256) void k_softmax_row(const float* __restrict__ in,
                                                     bf16* __restrict__ oh, bf16* __restrict__ ol)
{
    const size_t off = (size_t)blockIdx.x * HW;
    const float* __restrict__ row = in + off;
    const int t = threadIdx.x;
    __shared__ float red[256];

    float m = -1e30f;
    for (int i = t; i < HW; i += 256) m = fmaxf(m, row[i]);
    red[t] = m; __syncthreads();
    for (int s = 128; s > 0; s >>= 1) {
        if (t < s) red[t] = fmaxf(red[t], red[t + s]);
        __syncthreads();
    }
    m = red[0]; __syncthreads();

    float sum = 0.f;
    for (int i = t; i < HW; i += 256) sum += __expf(row[i] - m);
    red[t] = sum; __syncthreads();
    for (int s = 128; s > 0; s >>= 1) {
        if (t < s) red[t] += red[t + s];
        __syncthreads();
    }
    const float inv = 1.0f / red[0];
    for (int i = t; i < HW; i += 256) {
        const float v = __expf(row[i] - m) * inv;
        uint16_t hh, ll;
        split1(v, hh, ll);
        ((uint16_t*)oh)[off + i] = hh;
        ((uint16_t*)ol)[off + i] = ll;
    }
}

__global__ __launch_bounds__(256) void k_softmax128(const float* __restrict__ in,
                                                    bf16* __restrict__ oh, bf16* __restrict__ ol,
                                                    int nrows)
{
    const int row = (blockIdx.x * blockDim.x + threadIdx.x) >> 5;
    if (row >= nrows) return;
    const int lane = threadIdx.x & 31;
    const float4 v = *((const float4*)(in + (size_t)row * CN) + lane);

    float m = fmaxf(fmaxf(v.x, v.y), fmaxf(v.z, v.w));
    #pragma unroll
    for (int o = 16; o > 0; o >>= 1) m = fmaxf(m, __shfl_xor_sync(0xFFFFFFFFu, m, o));

    float ex = __expf(v.x - m), ey = __expf(v.y - m);
    float ez = __expf(v.z - m), ew = __expf(v.w - m);
    float s = ex + ey + ez + ew;
    #pragma unroll
    for (int o = 16; o > 0; o >>= 1) s += __shfl_xor_sync(0xFFFFFFFFu, s, o);

    const float inv = 1.0f / s;
    uint32_t h01, l01, h23, l23;
    split2(ex * inv, ey * inv, h01, l01);
    split2(ez * inv, ew * inv, h23, l23);
    const size_t off = (size_t)row * CN + lane * 4;
    *(uint2*)((uint16_t*)oh + off) = make_uint2(h01, h23);
    *(uint2*)((uint16_t*)ol + off) = make_uint2(l01, l23);
}

// ---------------------------------------------------------------------------
// Pipelined bf16 split-float GEMM: D[m][n] = sum_k A[m][k]*B[n][k]
//   Block tile 128x64, K-chunk 32, 2-stage cp.async double buffer.
//   8 warps (4m x 2n), warp tile 32x32, m16n8k16, 3-MMA split accumulation.
//   outmode: 0 = fp32 C[m*ldc+n], 1 = fp32 C[n*ldc+m],
//            2 = split bf16 trans (Ch/Cl [n*ldc+m]), 3 = split bf16 normal.
// ---------------------------------------------------------------------------
#define APITCH 40                       // bf16/row (80B) -> conflict-free ldmatrix
#define ST_AH 0
#define ST_AL (128 * APITCH)
#define ST_BH (256 * APITCH)
#define ST_BL (256 * APITCH + 64 * APITCH)
#define ST_ELEMS (384 * APITCH)         // 15360 bf16 = 30720 B per stage
#define EPITCH 68
#define SMEM_BYTES (2 * ST_ELEMS * 2)   // 61440 B (epilogue 34816 B fits inside)

__global__ __launch_bounds__(256) void k_mma(
    const bf16* __restrict__ Ah, const bf16* __restrict__ Al,
    const bf16* __restrict__ Bh, const bf16* __restrict__ Bl,
    void* __restrict__ Cv, void* __restrict__ Clv,
    const float* __restrict__ bias,
    int Kd, int ldc, int outmode,
    long long sA, long long sB, long long sC)
{
    extern __shared__ __align__(16) char smraw[];
    const int b = blockIdx.z;
    Ah += (size_t)b * sA; Al += (size_t)b * sA;
    Bh += (size_t)b * sB; Bl += (size_t)b * sB;
    const int m0 = blockIdx.y * 128;
    const int n0 = blockIdx.x * 64;
    const int tid = threadIdx.x, wid = tid >> 5, lane = tid & 31;
    const int warp_m = wid & 3, warp_n = wid >> 2;
    const uint32_t sbase = smem_u32(smraw);
    const int lrow = lane & 15, lgr = lane >> 4;

    auto load_stage = [&](int s, int k0) {
        const uint32_t base = sbase + (uint32_t)s * (ST_ELEMS * 2);
        #pragma unroll
        for (int i = tid; i < 512; i += 256) {
            const int r = i >> 2, c = (i & 3) << 3;   // c in bf16 elems (0,8,16,24)
            const size_t gs = (size_t)(m0 + r) * Kd + k0 + c;
            cp16(base + (uint32_t)(ST_AH + r * APITCH + c) * 2, Ah + gs);
            cp16(base + (uint32_t)(ST_AL + r * APITCH + c) * 2, Al + gs);
        }
        #pragma unroll
        for (int i = tid; i < 256; i += 256) {
            const int r = i >> 2, c = (i & 3) << 3;
            const size_t gs = (size_t)(n0 + r) * Kd + k0 + c;
            cp16(base + (uint32_t)(ST_BH + r * APITCH + c) * 2, Bh + gs);
            cp16(base + (uint32_t)(ST_BL + r * APITCH + c) * 2, Bl + gs);
        }
    };

    float acc[2][4][4] = {};
    const int nchunk = Kd >> 5;

    load_stage(0, 0);
    CP_COMMIT();

    for (int ch = 0; ch < nchunk; ++ch) {
        if (ch + 1 < nchunk) load_stage((ch + 1) & 1, (ch + 1) << 5);
        CP_COMMIT();
        CP_WAIT1();
        __syncthreads();

        const uint32_t stb = sbase + (uint32_t)(ch & 1) * (ST_ELEMS * 2);
        #pragma unroll
        for (int ks = 0; ks < 2; ++ks) {
            const uint32_t goff = (uint32_t)((ks * 2 + lgr) * 16);  // bytes
            uint32_t ah[2][4], al[2][4];
            #pragma unroll
            for (int mt = 0; mt < 2; ++mt) {
                const int row = warp_m * 32 + mt * 16 + lrow;
                ldsm_x4(ah[mt][0], ah[mt][1], ah[mt][2], ah[mt][3],
                        stb + (ST_AH + row * APITCH) * 2 + goff);
                ldsm_x4(al[mt][0], al[mt][1], al[mt][2], al[mt][3],
                        stb + (ST_AL + row * APITCH) * 2 + goff);
            }
            uint32_t bh[4][2], bl[4][2];
            #pragma unroll
            for (int ng = 0; ng < 2; ++ng) {
                const int row = warp_n * 32 + ng * 16 + lrow;
                uint32_t r0, r1, r2, r3;
                ldsm_x4(r0, r1, r2, r3, stb + (ST_BH + row * APITCH) * 2 + goff);
                bh[ng * 2 + 0][0] = r0; bh[ng * 2 + 0][1] = r2;
                bh[ng * 2 + 1][0] = r1; bh[ng * 2 + 1][1] = r3;
                ldsm_x4(r0, r1, r2, r3, stb + (ST_BL + row * APITCH) * 2 + goff);
                bl[ng * 2 + 0][0] = r0; bl[ng * 2 + 0][1] = r2;
                bl[ng * 2 + 1][0] = r1; bl[ng * 2 + 1][1] = r3;
            }
            #pragma unroll
            for (int mt = 0; mt < 2; ++mt)
                #pragma unroll
                for (int nt = 0; nt < 4; ++nt) {
                    mma16816(acc[mt][nt], ah[mt], bh[nt][0], bh[nt][1]);
                    mma16816(acc[mt][nt], ah[mt], bl[nt][0], bl[nt][1]);
                    mma16816(acc[mt][nt], al[mt], bh[nt][0], bh[nt][1]);
                }
        }
        __syncthreads();
    }
    CP_WAIT0();
    __syncthreads();

    // ---- epilogue: stage fp32 (+bias) in SMEM, then coalesced stores ----
    float* const st = (float*)smraw;   // [128][EPITCH]
    {
        const int drow = lane >> 2, dcol = (lane & 3) * 2;
        #pragma unroll
        for (int mt = 0; mt < 2; ++mt) {
            const int r0w = warp_m * 32 + mt * 16 + drow;
            const float bv0 = bias ? bias[m0 + r0w]     : 0.0f;
            const float bv1 = bias ? bias[m0 + r0w + 8] : 0.0f;
            #pragma unroll
            for (int nt = 0; nt < 4; ++nt) {
                const int c = warp_n * 32 + nt * 8 + dcol;
                st[r0w * EPITCH + c]           = acc[mt][nt][0] + bv0;
                st[r0w * EPITCH + c + 1]       = acc[mt][nt][1] + bv0;
                st[(r0w + 8) * EPITCH + c]     = acc[mt][nt][2] + bv1;
                st[(r0w + 8) * EPITCH + c + 1] = acc[mt][nt][3] + bv1;
            }
        }
    }
    __syncthreads();

    if (outmode == 0) {
        float* C = (float*)Cv + (size_t)b * sC;
        for (int i = tid; i < 128 * 16; i += 256) {
            const int r = i >> 4, q = (i & 15) << 2;
            float4 v = make_float4(st[r * EPITCH + q],     st[r * EPITCH + q + 1],
                                   st[r * EPITCH + q + 2], st[r * EPITCH + q + 3]);
            *(float4*)&C[(size_t)(m0 + r) * ldc + n0 + q] = v;
        }
    } else if (outmode == 1) {
        float* C = (float*)Cv + (size_t)b * sC;
        for (int i = tid; i < 64 * 32; i += 256) {
            const int n = i >> 5, mq = (i & 31) << 2;
            float4 v = make_float4(st[(mq + 0) * EPITCH + n], st[(mq + 1) * EPITCH + n],
                                   st[(mq + 2) * EPITCH + n], st[(mq + 3) * EPITCH + n]);
            *(float4*)&C[(size_t)(n0 + n) * ldc + m0 + mq] = v;
        }
    } else if (outmode == 2) {
        uint16_t* Ch = (uint16_t*)Cv  + (size_t)b * sC;
        uint16_t* Cl = (uint16_t*)Clv + (size_t)b * sC;
        for (int i = tid; i < 64 * 32; i += 256) {
            const int n = i >> 5, mq = (i & 31) << 2;
            uint32_t h0, l0, h1, l1;
            split2(st[(mq + 0) * EPITCH + n], st[(mq + 1) * EPITCH + n], h0, l0);
            split2(st[(mq + 2) * EPITCH + n], st[(mq + 3) * EPITCH + n], h1, l1);
            const size_t off = (size_t)(n0 + n) * ldc + m0 + mq;
            *(uint2*)(Ch + off) = make_uint2(h0, h1);
            *(uint2*)(Cl + off) = make_uint2(l0, l1);
        }
    } else {
        uint16_t* Ch = (uint16_t*)Cv  + (size_t)b * sC;
        uint16_t* Cl = (uint16_t*)Clv + (size_t)b * sC;
        for (int i = tid; i < 128 * 16; i += 256) {
            const int r = i >> 4, q = (i & 15) << 2;
            uint32_t h0, l0, h1, l1;
            split2(st[r * EPITCH + q],     st[r * EPITCH + q + 1], h0, l0);
            split2(st[r * EPITCH + q + 2], st[r * EPITCH + q + 3], h1, l1);
            const size_t off = (size_t)(m0 + r) * ldc + n0 + q;
            *(uint2*)(Ch + off) = make_uint2(h0, h1);
            *(uint2*)(Cl + off) = make_uint2(l0, l1);
        }
    }
}

// ---------------------------------------------------------------------------
// Launch
// ---------------------------------------------------------------------------
extern "C" void kernel_launch(void* const* d_in, const int* in_sizes, int n_in,
                              void* d_out, int out_size)
{
    const float* x  = (const float*)d_in[0];
    const float* wA = (const float*)d_in[1];
    const float* bA = (const float*)d_in[2];
    const float* wB = (const float*)d_in[3];
    const float* bB = (const float*)d_in[4];
    const float* wV = (const float*)d_in[5];
    const float* bV = (const float*)d_in[6];
    float* out = (float*)d_out;

    bf16 *wAh, *wAl, *wBh, *wBl, *wVh, *wVl;
    bf16 *xh, *xl, *xTh, *xTl, *aBh, *aBl, *aVh, *aVl, *xBTh, *xBTl, *Gh, *Gl;
    float *Bf, *Vf;
    cudaGetSymbolAddress((void**)&wAh, g_wAh); cudaGetSymbolAddress((void**)&wAl, g_wAl);
    cudaGetSymbolAddress((void**)&wBh, g_wBh); cudaGetSymbolAddress((void**)&wBl, g_wBl);
    cudaGetSymbolAddress((void**)&wVh, g_wVh); cudaGetSymbolAddress((void**)&wVl, g_wVl);
    cudaGetSymbolAddress((void**)&xh,  g_xh);  cudaGetSymbolAddress((void**)&xl,  g_xl);
    cudaGetSymbolAddress((void**)&xTh, g_xTh); cudaGetSymbolAddress((void**)&xTl, g_xTl);
    cudaGetSymbolAddress((void**)&Bf,  g_Bf);  cudaGetSymbolAddress((void**)&Vf,  g_Vf);
    cudaGetSymbolAddress((void**)&aBh, g_aBh); cudaGetSymbolAddress((void**)&aBl, g_aBl);
    cudaGetSymbolAddress((void**)&aVh, g_aVh); cudaGetSymbolAddress((void**)&aVl, g_aVl);
    cudaGetSymbolAddress((void**)&xBTh, g_xBTh); cudaGetSymbolAddress((void**)&xBTl, g_xBTl);
    cudaGetSymbolAddress((void**)&Gh,  g_Gh);  cudaGetSymbolAddress((void**)&Gl,  g_Gl);

    cudaFuncSetAttribute(k_mma, cudaFuncAttributeMaxDynamicSharedMemorySize, SMEM_BYTES);

    // prep: split weights; split+transpose x
    k_split<<<(CM * CIN + 255) / 256, 256>>>(wA, wAh, wAl, CM * CIN);
    k_split<<<(CN * CIN + 255) / 256, 256>>>(wB, wBh, wBl, CN * CIN);
    k_split<<<(CN * CIN + 255) / 256, 256>>>(wV, wVh, wVl, CN * CIN);
    k_prepx<<<dim3(HW / 32, CIN / 32, NBATCH), 256>>>(x, xh, xl, xTh, xTl);

    // K1-B: Bf = wB @ x + bB    (M=128, N=HW, K=512) -> fp32 [b][n][p]
    k_mma<<<dim3(HW / 64, 1, NBATCH), 256, SMEM_BYTES>>>(
        wBh, wBl, xTh, xTl, Bf, nullptr, bB, CIN, HW, 0,
        0, (long long)HW * CIN, (long long)CN * HW);

    // K1-V: Vf = wV @ x + bV -> fp32 trans [b][p][n]
    k_mma<<<dim3(HW / 64, 1, NBATCH), 256, SMEM_BYTES>>>(
        wVh, wVl, xTh, xTl, Vf, nullptr, bV, CIN, CN, 1,
        0, (long long)HW * CIN, (long long)HW * CN);

    // softmaxes -> split bf16
    k_softmax_row<<<NBATCH * CN, 256>>>(Bf, aBh, aBl);
    {
        const int nrows  = NBATCH * HW;
        const int blocks = (nrows * 32 + 255) / 256;
        k_softmax128<<<blocks, 256>>>(Vf, aVh, aVl, nrows);
    }

    // K4: xBT[n][c] = sum_p x[c][p]*attB[n][p]  (M=512, N=128, K=HW) -> split trans
    k_mma<<<dim3(CN / 64, CIN / 128, NBATCH), 256, SMEM_BYTES>>>(
        xh, xl, aBh, aBl, xBTh, xBTl, nullptr, HW, CIN, 2,
        (long long)CIN * HW, (long long)CN * HW, (long long)CN * CIN);

    // K5: G = wA @ xB + bA  (M=512, N=128, K=512) -> split normal
    k_mma<<<dim3(CN / 64, CM / 128, NBATCH), 256, SMEM_BYTES>>>(
        wAh, wAl, xBTh, xBTl, Gh, Gl, bA, CIN, CN, 3,
        0, (long long)CN * CIN, (long long)CM * CN);

    // K6: Z[m][p] = sum_n G[m][n]*attV[p][n]  (M=512, N=HW, K=128) -> fp32 out
    k_mma<<<dim3(HW / 64, CM / 128, NBATCH), 256, SMEM_BYTES>>>(
        Gh, Gl, aVh, aVl, out, nullptr, nullptr, CN, HW, 0,
        (long long)CM * CN, (long long)HW * CN, (long long)CM * HW);

    (void)in_sizes; (void)n_in; (void)out_size;
}

// round 5
// speedup vs baseline: 2.2832x; 1.0575x over previous
#include <cuda_runtime.h>
#include <cuda_bf16.h>
#include <cstdint>

#define NBATCH 16
#define CIN    512
#define CM     512
#define CN     128
#define HW     3136   // 56*56 = 49*64

typedef __nv_bfloat16 bf16;

// ---------------------------------------------------------------------------
// Scratch
// ---------------------------------------------------------------------------
__device__ bf16 g_wAh [CM * CIN],      g_wAl [CM * CIN];
__device__ bf16 g_wBVh[2 * CN * CIN],  g_wBVl[2 * CN * CIN];   // wB rows 0-127, wV rows 128-255
__device__ float g_bBV[2 * CN];
__device__ bf16 g_xh [NBATCH * (size_t)CIN * HW], g_xl [NBATCH * (size_t)CIN * HW];
__device__ float g_Bf[NBATCH * (size_t)CN * HW];   // pre-softmax B  [b][n][p]
__device__ float g_Vf[NBATCH * (size_t)HW * CN];   // pre-softmax V  [b][p][n]
__device__ bf16 g_aBh[NBATCH * (size_t)CN * HW],  g_aBl[NBATCH * (size_t)CN * HW];
__device__ bf16 g_aVh[NBATCH * (size_t)HW * CN],  g_aVl[NBATCH * (size_t)HW * CN];
__device__ bf16 g_xBTh[NBATCH * (size_t)CN * CIN], g_xBTl[NBATCH * (size_t)CN * CIN];
__device__ bf16 g_Gh [NBATCH * (size_t)CM * CN],  g_Gl [NBATCH * (size_t)CM * CN];

// ---------------------------------------------------------------------------
// helpers
// ---------------------------------------------------------------------------
__device__ __forceinline__ uint32_t smem_u32(const void* p) {
    uint32_t a;
    asm("{ .reg .u64 t; cvta.to.shared.u64 t, %1; cvt.u32.u64 %0, t; }"
        : "=r"(a) : "l"(p));
    return a;
}
__device__ __forceinline__ void split1(float f, uint16_t& hi, uint16_t& lo) {
    __nv_bfloat16 h = __float2bfloat16_rn(f);
    float r = f - __bfloat162float(h);
    __nv_bfloat16 l = __float2bfloat16_rn(r);
    hi = __bfloat16_as_ushort(h);
    lo = __bfloat16_as_ushort(l);
}
__device__ __forceinline__ void split2(float f0, float f1, uint32_t& hi, uint32_t& lo) {
    uint16_t h0, l0, h1, l1;
    split1(f0, h0, l0);
    split1(f1, h1, l1);
    hi = (uint32_t)h0 | ((uint32_t)h1 << 16);
    lo = (uint32_t)l0 | ((uint32_t)l1 << 16);
}

__device__ __forceinline__ void cp16(uint32_t dst, const void* src) {
    asm volatile("cp.async.cg.shared.global [%0], [%1], 16;" :: "r"(dst), "l"(src));
}
#define CP_COMMIT() asm volatile("cp.async.commit_group;")
#define CP_WAIT1()  asm volatile("cp.async.wait_group 1;")
#define CP_WAIT0()  asm volatile("cp.async.wait_group 0;")

__device__ __forceinline__ void ldsm_x4(uint32_t& r0, uint32_t& r1,
                                        uint32_t& r2, uint32_t& r3, uint32_t addr) {
    asm volatile("ldmatrix.sync.aligned.m8n8.x4.shared.b16 {%0,%1,%2,%3}, [%4];"
                 : "=r"(r0), "=r"(r1), "=r"(r2), "=r"(r3) : "r"(addr));
}
__device__ __forceinline__ void ldsm_x4t(uint32_t& r0, uint32_t& r1,
                                         uint32_t& r2, uint32_t& r3, uint32_t addr) {
    asm volatile("ldmatrix.sync.aligned.m8n8.x4.trans.shared.b16 {%0,%1,%2,%3}, [%4];"
                 : "=r"(r0), "=r"(r1), "=r"(r2), "=r"(r3) : "r"(addr));
}
__device__ __forceinline__ void mma16816(float* d, const uint32_t* a,
                                         uint32_t b0, uint32_t b1) {
    asm volatile(
        "mma.sync.aligned.m16n8k16.row.col.f32.bf16.bf16.f32 "
        "{%0,%1,%2,%3}, {%4,%5,%6,%7}, {%8,%9}, {%0,%1,%2,%3};"
        : "+f"(d[0]), "+f"(d[1]), "+f"(d[2]), "+f"(d[3])
        : "r"(a[0]), "r"(a[1]), "r"(a[2]), "r"(a[3]), "r"(b0), "r"(b1));
}

// ---------------------------------------------------------------------------
// Streaming split (float4 -> two bf16x4)
// ---------------------------------------------------------------------------
__global__ __launch_bounds__(256) void k_splitv(const float4* __restrict__ src,
                                                uint2* __restrict__ h, uint2* __restrict__ l,
                                                int n4)
{
    const int i = blockIdx.x * 256 + threadIdx.x;
    if (i < n4) {
        const float4 v = src[i];
        uint32_t h0, l0, h1, l1;
        split2(v.x, v.y, h0, l0);
        split2(v.z, v.w, h1, l1);
        h[i] = make_uint2(h0, h1);
        l[i] = make_uint2(l0, l1);
    }
}

// ---------------------------------------------------------------------------
// Softmaxes -> split bf16
// ---------------------------------------------------------------------------
__global__ __launch_bounds__(256) void k_softmax_row(const float* __restrict__ in,
                                                     bf16* __restrict__ oh, bf16* __restrict__ ol)
{
    const size_t off = (size_t)blockIdx.x * HW;
    const float* __restrict__ row = in + off;
    const int t = threadIdx.x;
    __shared__ float red[256];

    float v[13];
    float m = -1e30f;
    #pragma unroll
    for (int j = 0; j < 13; ++j) {
        const int i = j * 256 + t;
        if (i < HW) { v[j] = row[i]; m = fmaxf(m, v[j]); }
        else v[j] = -1e30f;
    }
    red[t] = m; __syncthreads();
    for (int s = 128; s > 0; s >>= 1) {
        if (t < s) red[t] = fmaxf(red[t], red[t + s]);
        __syncthreads();
    }
    m = red[0]; __syncthreads();

    float sum = 0.f;
    #pragma unroll
    for (int j = 0; j < 13; ++j) {
        v[j] = __expf(v[j] - m);
        sum += v[j];
    }
    red[t] = sum; __syncthreads();
    for (int s = 128; s > 0; s >>= 1) {
        if (t < s) red[t] += red[t + s];
        __syncthreads();
    }
    const float inv = 1.0f / red[0];
    #pragma unroll
    for (int j = 0; j < 13; ++j) {
        const int i = j * 256 + t;
        if (i < HW) {
            uint16_t hh, ll;
            split1(v[j] * inv, hh, ll);
            ((uint16_t*)oh)[off + i] = hh;
            ((uint16_t*)ol)[off + i] = ll;
        }
    }
}

__global__ __launch_bounds__(256) void k_softmax128(const float* __restrict__ in,
                                                    bf16* __restrict__ oh, bf16* __restrict__ ol,
                                                    int nrows)
{
    const int row = (blockIdx.x * blockDim.x + threadIdx.x) >> 5;
    if (row >= nrows) return;
    const int lane = threadIdx.x & 31;
    const float4 v = *((const float4*)(in + (size_t)row * CN) + lane);

    float m = fmaxf(fmaxf(v.x, v.y), fmaxf(v.z, v.w));
    #pragma unroll
    for (int o = 16; o > 0; o >>= 1) m = fmaxf(m, __shfl_xor_sync(0xFFFFFFFFu, m, o));

    float ex = __expf(v.x - m), ey = __expf(v.y - m);
    float ez = __expf(v.z - m), ew = __expf(v.w - m);
    float s = ex + ey + ez + ew;
    #pragma unroll
    for (int o = 16; o > 0; o >>= 1) s += __shfl_xor_sync(0xFFFFFFFFu, s, o);

    const float inv = 1.0f / s;
    uint32_t h01, l01, h23, l23;
    split2(ex * inv, ey * inv, h01, l01);
    split2(ez * inv, ew * inv, h23, l23);
    const size_t off = (size_t)row * CN + lane * 4;
    *(uint2*)((uint16_t*)oh + off) = make_uint2(h01, h23);
    *(uint2*)((uint16_t*)ol + off) = make_uint2(l01, l23);
}

// ---------------------------------------------------------------------------
// Pipelined bf16 split-float GEMM: D[m][n] = sum_k A[m][k]*B[n][k]
//   Block tile 128x64, K-chunk 32, 3-stage cp.async, one __syncthreads/chunk.
//   bmode 0: B K-major rows (stride ldb);  bmode 1: B = Bp[k*ldb + n] (trans
//            ldmatrix from [k][n] SMEM tiles).
//   outmode 0: fp32 C[m*ldc+n]      1: fp32 C[n*ldc+m]
//           2: split bf16 trans     3: split bf16 normal
//           4: merged (y==0 -> mode0 into Cv; y==1 -> mode1 into C2v/ldc2)
// ---------------------------------------------------------------------------
#define APITCH 40
#define BPITCH 72
#define ST_AH  0
#define ST_AL  (128 * APITCH)                    // 5120
#define ST_B0H (256 * APITCH)                    // 10240
#define ST_B0L (256 * APITCH + 64 * APITCH)      // 12800
#define ST_B1H (256 * APITCH)                    // 10240
#define ST_B1L (256 * APITCH + 32 * BPITCH)      // 12544
#define ST_ELEMS 15360
#define STAGE_BYTES (ST_ELEMS * 2)
#define NSTAGE 3
#define SMEM_BYTES (NSTAGE * STAGE_BYTES)        // 92160
#define EPITCH 68

__global__ __launch_bounds__(256) void k_mma(
    const bf16* __restrict__ Ah, const bf16* __restrict__ Al,
    const bf16* __restrict__ Bh, const bf16* __restrict__ Bl,
    void* __restrict__ Cv, void* __restrict__ C2v,
    const float* __restrict__ bias,
    int Kd, int ldb, int ldc, int ldc2, int outmode, int bmode,
    long long sA, long long sB, long long sC, long long sC2)
{
    extern __shared__ __align__(16) char smraw[];
    const int b = blockIdx.z;
    Ah += (size_t)b * sA; Al += (size_t)b * sA;
    Bh += (size_t)b * sB; Bl += (size_t)b * sB;
    const int m0 = blockIdx.y * 128;
    const int n0 = blockIdx.x * 64;
    const int tid = threadIdx.x, wid = tid >> 5, lane = tid & 31;
    const int warp_m = wid & 3, warp_n = wid >> 2;
    const uint32_t sbase = smem_u32(smraw);
    const int lrow = lane & 15, lgr = lane >> 4;

    auto load_stage = [&](int s, int k0) {
        const uint32_t base = sbase + (uint32_t)s * STAGE_BYTES;
        #pragma unroll
        for (int i = tid; i < 512; i += 256) {
            const int r = i >> 2, c = (i & 3) << 3;
            const size_t gs = (size_t)(m0 + r) * Kd + k0 + c;
            cp16(base + (uint32_t)(ST_AH + r * APITCH + c) * 2, Ah + gs);
            cp16(base + (uint32_t)(ST_AL + r * APITCH + c) * 2, Al + gs);
        }
        if (bmode == 0) {
            {
                const int i = tid;
                if (i < 256) {
                    const int r = i >> 2, c = (i & 3) << 3;
                    const size_t gs = (size_t)(n0 + r) * ldb + k0 + c;
                    cp16(base + (uint32_t)(ST_B0H + r * APITCH + c) * 2, Bh + gs);
                    cp16(base + (uint32_t)(ST_B0L + r * APITCH + c) * 2, Bl + gs);
                }
            }
        } else {
            {
                const int i = tid;
                if (i < 256) {
                    const int r = i >> 3, c = (i & 7) << 3;   // 32 k-rows x 64 n
                    const size_t gs = (size_t)(k0 + r) * ldb + n0 + c;
                    cp16(base + (uint32_t)(ST_B1H + r * BPITCH + c) * 2, Bh + gs);
                    cp16(base + (uint32_t)(ST_B1L + r * BPITCH + c) * 2, Bl + gs);
                }
            }
        }
    };

    float acc[2][4][4] = {};
    const int nchunk = Kd >> 5;

    load_stage(0, 0); CP_COMMIT();
    load_stage(1, 32); CP_COMMIT();

    for (int ch = 0; ch < nchunk; ++ch) {
        CP_WAIT1();
        __syncthreads();
        if (ch + 2 < nchunk) load_stage((ch + 2) % NSTAGE, (ch + 2) << 5);
        CP_COMMIT();

        const uint32_t stb = sbase + (uint32_t)(ch % NSTAGE) * STAGE_BYTES;
        #pragma unroll
        for (int ks = 0; ks < 2; ++ks) {
            const uint32_t goff = (uint32_t)((ks * 2 + lgr) * 16);  // bytes
            uint32_t ah[2][4], al[2][4];
            #pragma unroll
            for (int mt = 0; mt < 2; ++mt) {
                const int row = warp_m * 32 + mt * 16 + lrow;
                ldsm_x4(ah[mt][0], ah[mt][1], ah[mt][2], ah[mt][3],
                        stb + (ST_AH + row * APITCH) * 2 + goff);
                ldsm_x4(al[mt][0], al[mt][1], al[mt][2], al[mt][3],
                        stb + (ST_AL + row * APITCH) * 2 + goff);
            }
            uint32_t bh[4][2], bl[4][2];
            if (bmode == 0) {
                #pragma unroll
                for (int ng = 0; ng < 2; ++ng) {
                    const int row = warp_n * 32 + ng * 16 + lrow;
                    uint32_t r0, r1, r2, r3;
                    ldsm_x4(r0, r1, r2, r3, stb + (ST_B0H + row * APITCH) * 2 + goff);
                    bh[ng * 2 + 0][0] = r0; bh[ng * 2 + 0][1] = r2;
                    bh[ng * 2 + 1][0] = r1; bh[ng * 2 + 1][1] = r3;
                    ldsm_x4(r0, r1, r2, r3, stb + (ST_B0L + row * APITCH) * 2 + goff);
                    bl[ng * 2 + 0][0] = r0; bl[ng * 2 + 0][1] = r2;
                    bl[ng * 2 + 1][0] = r1; bl[ng * 2 + 1][1] = r3;
                }
            } else {
                // trans: SMEM tile is [32 k][BPITCH n]; lanes address k-rows
                const int krow = ks * 16 + ((lane & 16) >> 1) + (lane & 7);
                #pragma unroll
                for (int ng = 0; ng < 2; ++ng) {
                    const int ncol = warp_n * 32 + ng * 16 + (lane & 8);
                    uint32_t r0, r1, r2, r3;
                    ldsm_x4t(r0, r1, r2, r3,
                             stb + (ST_B1H + krow * BPITCH + ncol) * 2);
                    bh[ng * 2 + 0][0] = r0; bh[ng * 2 + 0][1] = r2;
                    bh[ng * 2 + 1][0] = r1; bh[ng * 2 + 1][1] = r3;
                    ldsm_x4t(r0, r1, r2, r3,
                             stb + (ST_B1L + krow * BPITCH + ncol) * 2);
                    bl[ng * 2 + 0][0] = r0; bl[ng * 2 + 0][1] = r2;
                    bl[ng * 2 + 1][0] = r1; bl[ng * 2 + 1][1] = r3;
                }
            }
            #pragma unroll
            for (int mt = 0; mt < 2; ++mt)
                #pragma unroll
                for (int nt = 0; nt < 4; ++nt) {
                    mma16816(acc[mt][nt], ah[mt], bh[nt][0], bh[nt][1]);
                    mma16816(acc[mt][nt], ah[mt], bl[nt][0], bl[nt][1]);
                    mma16816(acc[mt][nt], al[mt], bh[nt][0], bh[nt][1]);
                }
        }
    }
    CP_WAIT0();
    __syncthreads();

    // ---- effective output mode ----
    int om = outmode;
    int m0out = m0;
    if (outmode == 4) {
        if (blockIdx.y == 0) om = 0;
        else { om = 1; m0out = 0; Cv = C2v; ldc = ldc2; sC = sC2; }
    }

    // ---- epilogue: stage fp32 (+bias) in SMEM, coalesced stores ----
    float* const st = (float*)smraw;   // [128][EPITCH]
    {
        const int drow = lane >> 2, dcol = (lane & 3) * 2;
        #pragma unroll
        for (int mt = 0; mt < 2; ++mt) {
            const int r0w = warp_m * 32 + mt * 16 + drow;
            const float bv0 = bias ? bias[m0 + r0w]     : 0.0f;
            const float bv1 = bias ? bias[m0 + r0w + 8] : 0.0f;
            #pragma unroll
            for (int nt = 0; nt < 4; ++nt) {
                const int c = warp_n * 32 + nt * 8 + dcol;
                st[r0w * EPITCH + c]           = acc[mt][nt][0] + bv0;
                st[r0w * EPITCH + c + 1]       = acc[mt][nt][1] + bv0;
                st[(r0w + 8) * EPITCH + c]     = acc[mt][nt][2] + bv1;
                st[(r0w + 8) * EPITCH + c + 1] = acc[mt][nt][3] + bv1;
            }
        }
    }
    __syncthreads();

    if (om == 0) {
        float* C = (float*)Cv + (size_t)b * sC;
        for (int i = tid; i < 128 * 16; i += 256) {
            const int r = i >> 4, q = (i & 15) << 2;
            float4 v = make_float4(st[r * EPITCH + q],     st[r * EPITCH + q + 1],
                                   st[r * EPITCH + q + 2], st[r * EPITCH + q + 3]);
            *(float4*)&C[(size_t)(m0out + r) * ldc + n0 + q] = v;
        }
    } else if (om == 1) {
        float* C = (float*)Cv + (size_t)b * sC;
        for (int i = tid; i < 64 * 32; i += 256) {
            const int n = i >> 5, mq = (i & 31) << 2;
            float4 v = make_float4(st[(mq + 0) * EPITCH + n], st[(mq + 1) * EPITCH + n],
                                   st[(mq + 2) * EPITCH + n], st[(mq + 3) * EPITCH + n]);
            *(float4*)&C[(size_t)(n0 + n) * ldc + m0out + mq] = v;
        }
    } else if (om == 2) {
        uint16_t* Ch = (uint16_t*)Cv  + (size_t)b * sC;
        uint16_t* Cl = (uint16_t*)C2v + (size_t)b * sC;
        for (int i = tid; i < 64 * 32; i += 256) {
            const int n = i >> 5, mq = (i & 31) << 2;
            uint32_t h0, l0, h1, l1;
            split2(st[(mq + 0) * EPITCH + n], st[(mq + 1) * EPITCH + n], h0, l0);
            split2(st[(mq + 2) * EPITCH + n], st[(mq + 3) * EPITCH + n], h1, l1);
            const size_t off = (size_t)(n0 + n) * ldc + m0out + mq;
            *(uint2*)(Ch + off) = make_uint2(h0, h1);
            *(uint2*)(Cl + off) = make_uint2(l0, l1);
        }
    } else {
        uint16_t* Ch = (uint16_t*)Cv  + (size_t)b * sC;
        uint16_t* Cl = (uint16_t*)C2v + (size_t)b * sC;
        for (int i = tid; i < 128 * 16; i += 256) {
            const int r = i >> 4, q = (i & 15) << 2;
            uint32_t h0, l0, h1, l1;
            split2(st[r * EPITCH + q],     st[r * EPITCH + q + 1], h0, l0);
            split2(st[r * EPITCH + q + 2], st[r * EPITCH + q + 3], h1, l1);
            const size_t off = (size_t)(m0out + r) * ldc + n0 + q;
            *(uint2*)(Ch + off) = make_uint2(h0, h1);
            *(uint2*)(Cl + off) = make_uint2(l0, l1);
        }
    }
}

// ---------------------------------------------------------------------------
// Launch
// ---------------------------------------------------------------------------
extern "C" void kernel_launch(void* const* d_in, const int* in_sizes, int n_in,
                              void* d_out, int out_size)
{
    const float* x  = (const float*)d_in[0];
    const float* wA = (const float*)d_in[1];
    const float* bA = (const float*)d_in[2];
    const float* wB = (const float*)d_in[3];
    const float* bB = (const float*)d_in[4];
    const float* wV = (const float*)d_in[5];
    const float* bV = (const float*)d_in[6];
    float* out = (float*)d_out;

    bf16 *wAh, *wAl, *wBVh, *wBVl, *xh, *xl;
    bf16 *aBh, *aBl, *aVh, *aVl, *xBTh, *xBTl, *Gh, *Gl;
    float *Bf, *Vf, *bBV;
    cudaGetSymbolAddress((void**)&wAh,  g_wAh);  cudaGetSymbolAddress((void**)&wAl,  g_wAl);
    cudaGetSymbolAddress((void**)&wBVh, g_wBVh); cudaGetSymbolAddress((void**)&wBVl, g_wBVl);
    cudaGetSymbolAddress((void**)&bBV,  g_bBV);
    cudaGetSymbolAddress((void**)&xh,   g_xh);   cudaGetSymbolAddress((void**)&xl,   g_xl);
    cudaGetSymbolAddress((void**)&Bf,   g_Bf);   cudaGetSymbolAddress((void**)&Vf,   g_Vf);
    cudaGetSymbolAddress((void**)&aBh,  g_aBh);  cudaGetSymbolAddress((void**)&aBl,  g_aBl);
    cudaGetSymbolAddress((void**)&aVh,  g_aVh);  cudaGetSymbolAddress((void**)&aVl,  g_aVl);
    cudaGetSymbolAddress((void**)&xBTh, g_xBTh); cudaGetSymbolAddress((void**)&xBTl, g_xBTl);
    cudaGetSymbolAddress((void**)&Gh,   g_Gh);   cudaGetSymbolAddress((void**)&Gl,   g_Gl);

    cudaFuncSetAttribute(k_mma, cudaFuncAttributeMaxDynamicSharedMemorySize, SMEM_BYTES);

    // ---- prep: split weights (wB|wV stacked), biases, x ----
    k_splitv<<<(CM * CIN / 4 + 255) / 256, 256>>>(
        (const float4*)wA, (uint2*)wAh, (uint2*)wAl, CM * CIN / 4);
    k_splitv<<<(CN * CIN / 4 + 255) / 256, 256>>>(
        (const float4*)wB, (uint2*)wBVh, (uint2*)wBVl, CN * CIN / 4);
    k_splitv<<<(CN * CIN / 4 + 255) / 256, 256>>>(
        (const float4*)wV, (uint2*)(wBVh + CN * CIN), (uint2*)(wBVl + CN * CIN), CN * CIN / 4);
    cudaMemcpyAsync(bBV,      bB, CN * sizeof(float), cudaMemcpyDeviceToDevice);
    cudaMemcpyAsync(bBV + CN, bV, CN * sizeof(float), cudaMemcpyDeviceToDevice);
    {
        const int n4 = NBATCH * CIN * HW / 4;
        k_splitv<<<(n4 + 255) / 256, 256>>>((const float4*)x, (uint2*)xh, (uint2*)xl, n4);
    }

    // ---- K1 merged: y=0 -> Bf = wB@x + bB (normal, [n][p]);
    //                 y=1 -> Vf = wV@x + bV (trans,  [p][n]).  B = x via trans-ldmatrix.
    k_mma<<<dim3(HW / 64, 2, NBATCH), 256, SMEM_BYTES>>>(
        wBVh, wBVl, xh, xl, Bf, Vf, bBV,
        CIN, /*ldb=*/HW, /*ldc=*/HW, /*ldc2=*/CN, /*outmode=*/4, /*bmode=*/1,
        0, (long long)CIN * HW, (long long)CN * HW, (long long)HW * CN);

    // ---- softmaxes ----
    k_softmax_row<<<NBATCH * CN, 256>>>(Bf, aBh, aBl);
    {
        const int nrows  = NBATCH * HW;
        const int blocks = (nrows * 32 + 255) / 256;
        k_softmax128<<<blocks, 256>>>(Vf, aVh, aVl, nrows);
    }

    // ---- K4: xBT[n][c] = sum_p x[c][p]*attB[n][p]  -> split bf16 trans ----
    k_mma<<<dim3(CN / 64, CIN / 128, NBATCH), 256, SMEM_BYTES>>>(
        xh, xl, aBh, aBl, xBTh, xBTl, nullptr,
        HW, /*ldb=*/HW, /*ldc=*/CIN, 0, /*outmode=*/2, /*bmode=*/0,
        (long long)CIN * HW, (long long)CN * HW, (long long)CN * CIN, 0);

    // ---- K5: G = wA @ xB + bA  -> split bf16 normal ----
    k_mma<<<dim3(CN / 64, CM / 128, NBATCH), 256, SMEM_BYTES>>>(
        wAh, wAl, xBTh, xBTl, Gh, Gl, bA,
        CIN, /*ldb=*/CIN, /*ldc=*/CN, 0, /*outmode=*/3, /*bmode=*/0,
        0, (long long)CN * CIN, (long long)CM * CN, 0);

    // ---- K6: Z[m][p] = sum_n G[m][n]*attV[p][n]  -> fp32 out ----
    k_mma<<<dim3(HW / 64, CM / 128, NBATCH), 256, SMEM_BYTES>>>(
        Gh, Gl, aVh, aVl, out, nullptr, nullptr,
        CN, /*ldb=*/CN, /*ldc=*/HW, 0, /*outmode=*/0, /*bmode=*/0,
        (long long)CM * CN, (long long)HW * CN, (long long)CM * HW, 0);

    (void)in_sizes; (void)n_in; (void)out_size;
}